// round 6
// baseline (speedup 1.0000x reference)
#include <cuda_runtime.h>
#include <cuda_bf16.h>
#include <math.h>

// Problem constants (fixed by the dataset)
#define NODES_MAX 100000
#define EDGES_MAX 1600000
#define F_IN   128
#define F_HID  64     // 32 float2
#define F_OUT  47
#define F_OUTP 48     // 24 float2 / 12 float4

#define SCAN_TPB 512          // must be >= number of scan blocks (196)

// ---------------------------------------------------------------------------
// Device scratch (no cudaMalloc allowed)
// ---------------------------------------------------------------------------
__device__ float g_y1 [NODES_MAX * F_HID];    // x @ W1, then scaled in-place by dinv
__device__ float g_h  [NODES_MAX * F_HID];    // hidden after layer 1
__device__ float g_y2 [NODES_MAX * F_OUTP];   // (h @ W2) * dinv[row], col 47 = 0
__device__ float g_dinv[NODES_MAX];
__device__ int   g_degi[NODES_MAX];
__device__ int   g_off [NODES_MAX + 1];
__device__ int   g_cursor[NODES_MAX];
__device__ int   g_csrc[EDGES_MAX];           // CSR by dst: source node ids
__device__ int   g_bsum [SCAN_TPB];

// ---------------------------------------------------------------------------
// CSR build
// ---------------------------------------------------------------------------
__global__ void zero_degi_kernel(int n) {
    int i = blockIdx.x * blockDim.x + threadIdx.x;
    if (i < n) g_degi[i] = 0;
}

__global__ void count_kernel(const int* __restrict__ dst, int e) {
    int i = blockIdx.x * blockDim.x + threadIdx.x;
    if (i < e) atomicAdd(&g_degi[__ldg(&dst[i])], 1);
}

// Stage 1: per-chunk (SCAN_TPB elems) partial sums.
__global__ __launch_bounds__(SCAN_TPB) void scan_partial_kernel(int n) {
    __shared__ int sred[SCAN_TPB];
    int t = threadIdx.x;
    int i = blockIdx.x * SCAN_TPB + t;
    sred[t] = (i < n) ? g_degi[i] : 0;
    __syncthreads();
    for (int o = SCAN_TPB / 2; o > 0; o >>= 1) {
        if (t < o) sred[t] += sred[t + o];
        __syncthreads();
    }
    if (t == 0) g_bsum[blockIdx.x] = sred[0];
}

// Stage 2 (fused tops+write): each block reduces the partials preceding it,
// then block-scans its own chunk and writes off/cursor/dinv.
__global__ __launch_bounds__(SCAN_TPB) void scan_write_kernel(int n, int e) {
    __shared__ int s[SCAN_TPB];
    __shared__ int base_sh;
    int t = threadIdx.x, bid = blockIdx.x;

    // base = sum of g_bsum[0 .. bid-1]   (bid <= 196 < SCAN_TPB)
    int v = (t < bid) ? g_bsum[t] : 0;
    s[t] = v;
    __syncthreads();
    for (int o = SCAN_TPB / 2; o > 0; o >>= 1) {
        if (t < o) s[t] += s[t + o];
        __syncthreads();
    }
    if (t == 0) base_sh = s[0];
    __syncthreads();
    int base = base_sh;
    __syncthreads();   // protect s[] reuse

    int i = bid * SCAN_TPB + t;
    int d = (i < n) ? g_degi[i] : 0;
    s[t] = d;
    __syncthreads();
    for (int o = 1; o < SCAN_TPB; o <<= 1) {
        int u = (t >= o) ? s[t - o] : 0;
        __syncthreads();
        s[t] += u;
        __syncthreads();
    }
    if (i < n) {
        int off = base + s[t] - d;     // exclusive prefix
        g_off[i] = off;
        g_cursor[i] = off;
        g_dinv[i] = rsqrtf((float)(d + 1));
    }
    if (bid == 0 && t == 0) g_off[n] = e;
}

__global__ void fill_kernel(const int* __restrict__ src, const int* __restrict__ dst, int e) {
    int i = blockIdx.x * blockDim.x + threadIdx.x;
    if (i < e) {
        int d = __ldg(&dst[i]);
        int pos = atomicAdd(&g_cursor[d], 1);
        g_csrc[pos] = __ldg(&src[i]);
    }
}

// ---------------------------------------------------------------------------
// GEMM1: y1[n,64] = x[n,128] @ W1[128,64]   (raw; dinv applied by scale_y1)
// ---------------------------------------------------------------------------
#define XS_LD 129
__global__ __launch_bounds__(256) void gemm1_kernel(const float* __restrict__ x,
                                                    const float* __restrict__ W1,
                                                    int n) {
    __shared__ float Ws[F_IN * F_HID];        // 32 KB, [k][c]
    __shared__ float Xs[32 * XS_LD];          // ~16.5 KB, [r][k] padded
    int tid = threadIdx.x;
    int row0 = blockIdx.x * 32;

    for (int i = tid; i < F_IN * F_HID; i += 256) Ws[i] = W1[i];
    for (int i = tid; i < 32 * F_IN; i += 256) {
        int r = i >> 7, k = i & 127;
        int gr = row0 + r;
        Xs[r * XS_LD + k] = (gr < n) ? x[gr * F_IN + k] : 0.f;
    }
    __syncthreads();

    int tx = tid & 15;        // cols tx*4 .. tx*4+3
    int ty = tid >> 4;        // 0..15, rows ty*2, ty*2+1
    float4 acc0 = make_float4(0.f, 0.f, 0.f, 0.f);
    float4 acc1 = make_float4(0.f, 0.f, 0.f, 0.f);
    const float4* Ws4 = reinterpret_cast<const float4*>(Ws);
    int r0 = ty * 2, r1 = ty * 2 + 1;
    #pragma unroll 4
    for (int k = 0; k < F_IN; k++) {
        float4 w = Ws4[k * 16 + tx];
        float a0 = Xs[r0 * XS_LD + k];
        float a1 = Xs[r1 * XS_LD + k];
        acc0.x = fmaf(a0, w.x, acc0.x); acc0.y = fmaf(a0, w.y, acc0.y);
        acc0.z = fmaf(a0, w.z, acc0.z); acc0.w = fmaf(a0, w.w, acc0.w);
        acc1.x = fmaf(a1, w.x, acc1.x); acc1.y = fmaf(a1, w.y, acc1.y);
        acc1.z = fmaf(a1, w.z, acc1.z); acc1.w = fmaf(a1, w.w, acc1.w);
    }
    int gr0 = row0 + r0, gr1 = row0 + r1;
    float4* y4 = reinterpret_cast<float4*>(g_y1);
    if (gr0 < n) y4[gr0 * 16 + tx] = acc0;
    if (gr1 < n) y4[gr1 * 16 + tx] = acc1;
}

// Scale y1 in place: z = y1 * dinv[row]. Runs on side stream, hidden by fill.
__global__ __launch_bounds__(256) void scale_y1_kernel(int n) {
    int i = blockIdx.x * blockDim.x + threadIdx.x;
    if (i >= n * 16) return;
    int r = i >> 4;
    float di = g_dinv[r];
    float4* y4 = reinterpret_cast<float4*>(g_y1);
    float4 v = y4[i];
    v.x *= di; v.y *= di; v.z *= di; v.w *= di;
    y4[i] = v;
}

// ---------------------------------------------------------------------------
// Aggregation layer 1 (warp per dst node):
//   h[d] = relu(dinv_d * (z[d] + sum_s z[s]) + b1)     (z = dinv*xW1)
// Lane l owns float2 (cols 2l, 2l+1). Unroll 8 for MLP.
// ---------------------------------------------------------------------------
__global__ __launch_bounds__(256) void agg1_kernel(const float* __restrict__ b1, int n) {
    int w = (blockIdx.x * blockDim.x + threadIdx.x) >> 5;
    int l = threadIdx.x & 31;
    if (w >= n) return;
    const float2* y = reinterpret_cast<const float2*>(g_y1);

    float2 acc = __ldg(&y[w * 32 + l]);   // self-loop term z[d]

    int beg = g_off[w], end = g_off[w + 1];
    for (int j = beg; j < end; j += 32) {
        int m = min(32, end - j);
        int idx = (l < m) ? __ldg(&g_csrc[j + l]) : 0;
        int t = 0;
        for (; t + 7 < m; t += 8) {
            int s0 = __shfl_sync(0xFFFFFFFFu, idx, t    );
            int s1 = __shfl_sync(0xFFFFFFFFu, idx, t + 1);
            int s2 = __shfl_sync(0xFFFFFFFFu, idx, t + 2);
            int s3 = __shfl_sync(0xFFFFFFFFu, idx, t + 3);
            int s4 = __shfl_sync(0xFFFFFFFFu, idx, t + 4);
            int s5 = __shfl_sync(0xFFFFFFFFu, idx, t + 5);
            int s6 = __shfl_sync(0xFFFFFFFFu, idx, t + 6);
            int s7 = __shfl_sync(0xFFFFFFFFu, idx, t + 7);
            float2 v0 = __ldg(&y[s0 * 32 + l]);
            float2 v1 = __ldg(&y[s1 * 32 + l]);
            float2 v2 = __ldg(&y[s2 * 32 + l]);
            float2 v3 = __ldg(&y[s3 * 32 + l]);
            float2 v4 = __ldg(&y[s4 * 32 + l]);
            float2 v5 = __ldg(&y[s5 * 32 + l]);
            float2 v6 = __ldg(&y[s6 * 32 + l]);
            float2 v7 = __ldg(&y[s7 * 32 + l]);
            acc.x += ((v0.x + v1.x) + (v2.x + v3.x)) + ((v4.x + v5.x) + (v6.x + v7.x));
            acc.y += ((v0.y + v1.y) + (v2.y + v3.y)) + ((v4.y + v5.y) + (v6.y + v7.y));
        }
        for (; t < m; t++) {
            int s0 = __shfl_sync(0xFFFFFFFFu, idx, t);
            float2 v = __ldg(&y[s0 * 32 + l]);
            acc.x += v.x; acc.y += v.y;
        }
    }
    float diw = g_dinv[w];
    float2 h;
    h.x = fmaxf(fmaf(diw, acc.x, __ldg(&b1[2 * l    ])), 0.f);
    h.y = fmaxf(fmaf(diw, acc.y, __ldg(&b1[2 * l + 1])), 0.f);
    reinterpret_cast<float2*>(g_h)[w * 32 + l] = h;
}

// ---------------------------------------------------------------------------
// GEMM2: y2[n,48] = (h[n,64] @ W2pad[64,48]) * dinv[row], col 47 = 0
// ---------------------------------------------------------------------------
#define HS_LD 65
__global__ __launch_bounds__(192) void gemm2_kernel(const float* __restrict__ W2, int n) {
    __shared__ float Ws[F_HID * F_OUTP];      // 12 KB, [k][c]
    __shared__ float Hs[64 * HS_LD];          // ~16.6 KB, [r][k] padded
    int tid = threadIdx.x;
    int row0 = blockIdx.x * 64;

    for (int i = tid; i < F_HID * F_OUTP; i += 192) {
        int k = i / F_OUTP, c = i - k * F_OUTP;
        Ws[i] = (c < F_OUT) ? W2[k * F_OUT + c] : 0.f;
    }
    for (int i = tid; i < 64 * F_HID; i += 192) {
        int r = i >> 6, k = i & 63;
        int gr = row0 + r;
        Hs[r * HS_LD + k] = (gr < n) ? g_h[gr * F_HID + k] : 0.f;
    }
    __syncthreads();

    int tx = tid % 12;        // cols tx*4..tx*4+3
    int ty = tid / 12;        // 0..15, rows ty*4..ty*4+3
    float4 acc[4];
    #pragma unroll
    for (int i = 0; i < 4; i++) acc[i] = make_float4(0.f, 0.f, 0.f, 0.f);
    const float4* Ws4 = reinterpret_cast<const float4*>(Ws);

    #pragma unroll 4
    for (int k = 0; k < F_HID; k++) {
        float4 wv = Ws4[k * 12 + tx];
        #pragma unroll
        for (int i = 0; i < 4; i++) {
            float a = Hs[(ty * 4 + i) * HS_LD + k];
            acc[i].x = fmaf(a, wv.x, acc[i].x);
            acc[i].y = fmaf(a, wv.y, acc[i].y);
            acc[i].z = fmaf(a, wv.z, acc[i].z);
            acc[i].w = fmaf(a, wv.w, acc[i].w);
        }
    }
    float4* y4 = reinterpret_cast<float4*>(g_y2);
    #pragma unroll
    for (int i = 0; i < 4; i++) {
        int r = row0 + ty * 4 + i;
        if (r < n) {
            float di = g_dinv[r];
            float4 v = acc[i];
            v.x *= di; v.y *= di; v.z *= di; v.w *= di;
            y4[r * 12 + tx] = v;
        }
    }
}

// ---------------------------------------------------------------------------
// Aggregation layer 2 + bias + log_softmax (warp per node, unroll 8):
//   z[d] = dinv[d]*(sum y2[s] + y2[d]) + b2 ; out = z - logsumexp(z)
// ---------------------------------------------------------------------------
__global__ __launch_bounds__(256) void agg2_kernel(const float* __restrict__ b2,
                                                   float* __restrict__ out, int n) {
    int w = (blockIdx.x * blockDim.x + threadIdx.x) >> 5;
    int l = threadIdx.x & 31;
    if (w >= n) return;
    const float2* y = reinterpret_cast<const float2*>(g_y2);
    bool act = (l < 24);
    int lc = act ? l : 0;     // safe column for inactive lanes

    float2 acc = make_float2(0.f, 0.f);
    if (act) acc = __ldg(&y[w * 24 + l]);   // self term (y2 pre-scaled by dinv)

    int beg = g_off[w], end = g_off[w + 1];
    for (int j = beg; j < end; j += 32) {
        int m = min(32, end - j);
        int idx = (l < m) ? __ldg(&g_csrc[j + l]) : 0;
        int t = 0;
        for (; t + 7 < m; t += 8) {
            int s0 = __shfl_sync(0xFFFFFFFFu, idx, t    );
            int s1 = __shfl_sync(0xFFFFFFFFu, idx, t + 1);
            int s2 = __shfl_sync(0xFFFFFFFFu, idx, t + 2);
            int s3 = __shfl_sync(0xFFFFFFFFu, idx, t + 3);
            int s4 = __shfl_sync(0xFFFFFFFFu, idx, t + 4);
            int s5 = __shfl_sync(0xFFFFFFFFu, idx, t + 5);
            int s6 = __shfl_sync(0xFFFFFFFFu, idx, t + 6);
            int s7 = __shfl_sync(0xFFFFFFFFu, idx, t + 7);
            if (act) {
                float2 v0 = __ldg(&y[s0 * 24 + lc]);
                float2 v1 = __ldg(&y[s1 * 24 + lc]);
                float2 v2 = __ldg(&y[s2 * 24 + lc]);
                float2 v3 = __ldg(&y[s3 * 24 + lc]);
                float2 v4 = __ldg(&y[s4 * 24 + lc]);
                float2 v5 = __ldg(&y[s5 * 24 + lc]);
                float2 v6 = __ldg(&y[s6 * 24 + lc]);
                float2 v7 = __ldg(&y[s7 * 24 + lc]);
                acc.x += ((v0.x + v1.x) + (v2.x + v3.x)) + ((v4.x + v5.x) + (v6.x + v7.x));
                acc.y += ((v0.y + v1.y) + (v2.y + v3.y)) + ((v4.y + v5.y) + (v6.y + v7.y));
            }
        }
        for (; t < m; t++) {
            int s0 = __shfl_sync(0xFFFFFFFFu, idx, t);
            if (act) {
                float2 v = __ldg(&y[s0 * 24 + lc]);
                acc.x += v.x; acc.y += v.y;
            }
        }
    }

    float di = g_dinv[w];
    float vx = -3.0e38f, vy = -3.0e38f;
    if (act) {
        vx = fmaf(di, acc.x, __ldg(&b2[2 * l]));
        if (2 * l + 1 < F_OUT) vy = fmaf(di, acc.y, __ldg(&b2[2 * l + 1]));
    }
    float m = fmaxf(vx, vy);
    #pragma unroll
    for (int o = 16; o > 0; o >>= 1)
        m = fmaxf(m, __shfl_xor_sync(0xFFFFFFFFu, m, o));
    float s = 0.f;
    if (act) {
        s = expf(vx - m);
        if (2 * l + 1 < F_OUT) s += expf(vy - m);
    }
    #pragma unroll
    for (int o = 16; o > 0; o >>= 1)
        s += __shfl_xor_sync(0xFFFFFFFFu, s, o);
    float lse = m + logf(s);

    if (act) {
        out[w * F_OUT + 2 * l] = vx - lse;
        if (2 * l + 1 < F_OUT) out[w * F_OUT + 2 * l + 1] = vy - lse;
    }
}

// ---------------------------------------------------------------------------
// Launch (side stream: gemm1 + dinv-scale overlap the CSR build)
// ---------------------------------------------------------------------------
extern "C" void kernel_launch(void* const* d_in, const int* in_sizes, int n_in,
                              void* d_out, int out_size) {
    const float* x  = (const float*)d_in[0];
    const int*   ei = (const int*)  d_in[1];
    const float* W1 = (const float*)d_in[2];
    const float* b1 = (const float*)d_in[3];
    const float* W2 = (const float*)d_in[4];
    const float* b2 = (const float*)d_in[5];
    float* out = (float*)d_out;

    int n = in_sizes[0] / F_IN;       // 100000
    int e = in_sizes[1] / 2;          // 1600000
    const int* src = ei;
    const int* dst = ei + e;

    static cudaStream_t s2 = nullptr;
    static cudaEvent_t ev_fork = nullptr, ev_scan = nullptr, ev_join = nullptr;
    if (s2 == nullptr) {
        cudaStreamCreateWithFlags(&s2, cudaStreamNonBlocking);
        cudaEventCreateWithFlags(&ev_fork, cudaEventDisableTiming);
        cudaEventCreateWithFlags(&ev_scan, cudaEventDisableTiming);
        cudaEventCreateWithFlags(&ev_join, cudaEventDisableTiming);
    }

    const int B = 256;
    int nb = (n + SCAN_TPB - 1) / SCAN_TPB;   // 196 <= SCAN_TPB

    // Fork: GEMM1 (independent of CSR build) on side stream
    cudaEventRecord(ev_fork, 0);
    cudaStreamWaitEvent(s2, ev_fork, 0);
    gemm1_kernel<<<(n + 31) / 32, 256, 0, s2>>>(x, W1, n);

    // Main stream: CSR build
    zero_degi_kernel<<<(n + B - 1) / B, B>>>(n);
    count_kernel<<<(e + B - 1) / B, B>>>(dst, e);
    scan_partial_kernel<<<nb, SCAN_TPB>>>(n);
    scan_write_kernel<<<nb, SCAN_TPB>>>(n, e);
    cudaEventRecord(ev_scan, 0);              // dinv/off ready
    fill_kernel<<<(e + B - 1) / B, B>>>(src, dst, e);

    // Side stream: scale y1 by dinv (needs gemm1 + scan; hidden under fill)
    cudaStreamWaitEvent(s2, ev_scan, 0);
    scale_y1_kernel<<<(n * 16 + B - 1) / B, B, 0, s2>>>(n);
    cudaEventRecord(ev_join, s2);

    // Join: agg1 needs CSR (main) and scaled y1 (s2)
    cudaStreamWaitEvent(0, ev_join, 0);

    agg1_kernel<<<(n * 32 + B - 1) / B, B>>>(b1, n);
    gemm2_kernel<<<(n + 63) / 64, 192>>>(W2, n);
    agg2_kernel<<<(n * 32 + B - 1) / B, B>>>(b2, out, n);
}

// round 8
// speedup vs baseline: 1.3797x; 1.3797x over previous
#include <cuda_runtime.h>
#include <cuda_bf16.h>
#include <cuda_fp16.h>
#include <math.h>

// Problem constants (fixed by the dataset)
#define NODES_MAX 100000
#define EDGES_MAX 1600000
#define F_IN   128
#define F_HID  64     // 32 half2 / 16 uint2
#define F_OUT  47
#define F_OUTP 48     // 24 half2 / 12 uint2

#define SCAN_TPB 512          // must be >= number of scan blocks (196)

// ---------------------------------------------------------------------------
// Device scratch (no cudaMalloc allowed)
// ---------------------------------------------------------------------------
__device__ __half g_y1h[NODES_MAX * F_HID];   // x @ W1 (raw, fp16)
__device__ float  g_h  [NODES_MAX * F_HID];   // hidden after layer 1 (fp32)
__device__ __half g_y2h[NODES_MAX * F_OUTP];  // (h @ W2) * dinv[row] (fp16), col 47 = 0
__device__ float  g_dinv[NODES_MAX];
__device__ int    g_degi[NODES_MAX];
__device__ int    g_off [NODES_MAX + 1];
__device__ int    g_cursor[NODES_MAX];
__device__ int    g_csrc[EDGES_MAX];          // CSR by dst: source node ids
__device__ int    g_bsum [SCAN_TPB];

// ---------------------------------------------------------------------------
// CSR build
// ---------------------------------------------------------------------------
__global__ void zero_degi_kernel(int n) {
    int i = blockIdx.x * blockDim.x + threadIdx.x;
    if (i < n) g_degi[i] = 0;
}

__global__ void count_kernel(const int* __restrict__ dst, int e) {
    int i = blockIdx.x * blockDim.x + threadIdx.x;
    if (i < e) atomicAdd(&g_degi[dst[i]], 1);
}

// Stage 1: per-chunk (SCAN_TPB elems) partial sums.
__global__ __launch_bounds__(SCAN_TPB) void scan_partial_kernel(int n) {
    __shared__ int sred[SCAN_TPB];
    int t = threadIdx.x;
    int i = blockIdx.x * SCAN_TPB + t;
    sred[t] = (i < n) ? g_degi[i] : 0;
    __syncthreads();
    for (int o = SCAN_TPB / 2; o > 0; o >>= 1) {
        if (t < o) sred[t] += sred[t + o];
        __syncthreads();
    }
    if (t == 0) g_bsum[blockIdx.x] = sred[0];
}

// Stage 2 (fused tops+write): each block reduces the partials preceding it,
// then block-scans its own chunk and writes off/cursor/dinv.
__global__ __launch_bounds__(SCAN_TPB) void scan_write_kernel(int n, int e) {
    __shared__ int s[SCAN_TPB];
    __shared__ int base_sh;
    int t = threadIdx.x, bid = blockIdx.x;

    int v = (t < bid) ? g_bsum[t] : 0;
    s[t] = v;
    __syncthreads();
    for (int o = SCAN_TPB / 2; o > 0; o >>= 1) {
        if (t < o) s[t] += s[t + o];
        __syncthreads();
    }
    if (t == 0) base_sh = s[0];
    __syncthreads();
    int base = base_sh;
    __syncthreads();   // protect s[] reuse

    int i = bid * SCAN_TPB + t;
    int d = (i < n) ? g_degi[i] : 0;
    s[t] = d;
    __syncthreads();
    for (int o = 1; o < SCAN_TPB; o <<= 1) {
        int u = (t >= o) ? s[t - o] : 0;
        __syncthreads();
        s[t] += u;
        __syncthreads();
    }
    if (i < n) {
        int off = base + s[t] - d;     // exclusive prefix
        g_off[i] = off;
        g_cursor[i] = off;
        g_dinv[i] = rsqrtf((float)(d + 1));
    }
    if (bid == 0 && t == 0) g_off[n] = e;
}

__global__ void fill_kernel(const int* __restrict__ src, const int* __restrict__ dst, int e) {
    int i = blockIdx.x * blockDim.x + threadIdx.x;
    if (i < e) {
        int d = dst[i];
        int pos = atomicAdd(&g_cursor[d], 1);
        g_csrc[pos] = src[i];
    }
}

// ---------------------------------------------------------------------------
// GEMM1: y1h[n,64] = fp16(x[n,128] @ W1[128,64])   (raw; dinv applied in agg1)
// ---------------------------------------------------------------------------
#define XS_LD 129
__global__ __launch_bounds__(256) void gemm1_kernel(const float* __restrict__ x,
                                                    const float* __restrict__ W1,
                                                    int n) {
    __shared__ float Ws[F_IN * F_HID];        // 32 KB, [k][c]
    __shared__ float Xs[32 * XS_LD];          // ~16.5 KB, [r][k] padded
    int tid = threadIdx.x;
    int row0 = blockIdx.x * 32;

    for (int i = tid; i < F_IN * F_HID; i += 256) Ws[i] = W1[i];
    for (int i = tid; i < 32 * F_IN; i += 256) {
        int r = i >> 7, k = i & 127;
        int gr = row0 + r;
        Xs[r * XS_LD + k] = (gr < n) ? x[gr * F_IN + k] : 0.f;
    }
    __syncthreads();

    int tx = tid & 15;        // cols tx*4 .. tx*4+3
    int ty = tid >> 4;        // 0..15, rows ty*2, ty*2+1
    float4 acc0 = make_float4(0.f, 0.f, 0.f, 0.f);
    float4 acc1 = make_float4(0.f, 0.f, 0.f, 0.f);
    const float4* Ws4 = reinterpret_cast<const float4*>(Ws);
    int r0 = ty * 2, r1 = ty * 2 + 1;
    #pragma unroll 4
    for (int k = 0; k < F_IN; k++) {
        float4 w = Ws4[k * 16 + tx];
        float a0 = Xs[r0 * XS_LD + k];
        float a1 = Xs[r1 * XS_LD + k];
        acc0.x = fmaf(a0, w.x, acc0.x); acc0.y = fmaf(a0, w.y, acc0.y);
        acc0.z = fmaf(a0, w.z, acc0.z); acc0.w = fmaf(a0, w.w, acc0.w);
        acc1.x = fmaf(a1, w.x, acc1.x); acc1.y = fmaf(a1, w.y, acc1.y);
        acc1.z = fmaf(a1, w.z, acc1.z); acc1.w = fmaf(a1, w.w, acc1.w);
    }
    int gr0 = row0 + r0, gr1 = row0 + r1;
    uint2* yp = reinterpret_cast<uint2*>(g_y1h);   // 16 uint2 per row
    if (gr0 < n) {
        __half2 p0 = __floats2half2_rn(acc0.x, acc0.y);
        __half2 p1 = __floats2half2_rn(acc0.z, acc0.w);
        uint2 u;
        u.x = *reinterpret_cast<unsigned int*>(&p0);
        u.y = *reinterpret_cast<unsigned int*>(&p1);
        yp[gr0 * 16 + tx] = u;
    }
    if (gr1 < n) {
        __half2 p0 = __floats2half2_rn(acc1.x, acc1.y);
        __half2 p1 = __floats2half2_rn(acc1.z, acc1.w);
        uint2 u;
        u.x = *reinterpret_cast<unsigned int*>(&p0);
        u.y = *reinterpret_cast<unsigned int*>(&p1);
        yp[gr1 * 16 + tx] = u;
    }
}

// ---------------------------------------------------------------------------
// Aggregation layer 1 (warp per dst node, fp16 gathers, edge-paired halves):
//   acc = dinv_d*y1[d] + sum_s dinv_s*y1[s] ; h[d] = relu(dinv_d*acc + b1)
// Half-warp h (lanes h*16..h*16+15) processes edge (t+h); lane covers 4 cols
// (one uint2 = 4 halfs). Fold across halves with shfl_xor(16) at the end.
// ---------------------------------------------------------------------------
__device__ __forceinline__ void acc4_fp16(float& f0, float& f1, float& f2, float& f3,
                                          uint2 a, float w) {
    __half2 h0 = *reinterpret_cast<__half2*>(&a.x);
    __half2 h1 = *reinterpret_cast<__half2*>(&a.y);
    float2 p0 = __half22float2(h0);
    float2 p1 = __half22float2(h1);
    f0 = fmaf(p0.x, w, f0); f1 = fmaf(p0.y, w, f1);
    f2 = fmaf(p1.x, w, f2); f3 = fmaf(p1.y, w, f3);
}

__global__ __launch_bounds__(256) void agg1_kernel(const float* __restrict__ b1, int n) {
    int w = (blockIdx.x * blockDim.x + threadIdx.x) >> 5;
    int l = threadIdx.x & 31;
    if (w >= n) return;
    int lh = l & 15, hh = l >> 4;
    const uint2* y = reinterpret_cast<const uint2*>(g_y1h);   // 16 per row

    float f0 = 0.f, f1 = 0.f, f2 = 0.f, f3 = 0.f;
    int beg = g_off[w], end = g_off[w + 1];
    for (int j = beg; j < end; j += 32) {
        int m = min(32, end - j);
        int idx = 0; float dv = 0.f;
        if (l < m) { idx = g_csrc[j + l]; dv = g_dinv[idx]; }
        int t = 0;
        // 2 paired steps per iteration = 4 edges, 2 LDG.64 in flight (MLP_p1=2)
        for (; t + 3 < m; t += 4) {
            int   eA = t + hh,       eB = t + 2 + hh;
            int   sA = __shfl_sync(0xFFFFFFFFu, idx, eA);
            float wA = __shfl_sync(0xFFFFFFFFu, dv,  eA);
            int   sB = __shfl_sync(0xFFFFFFFFu, idx, eB);
            float wB = __shfl_sync(0xFFFFFFFFu, dv,  eB);
            uint2 a = y[sA * 16 + lh];
            uint2 b = y[sB * 16 + lh];
            acc4_fp16(f0, f1, f2, f3, a, wA);
            acc4_fp16(f0, f1, f2, f3, b, wB);
        }
        // tail: 1-2 paired steps, phantom edges get weight 0
        for (; t < m; t += 2) {
            int   e0 = t + hh;
            int   se = min(e0, m - 1);
            int   s0 = __shfl_sync(0xFFFFFFFFu, idx, se);
            float w0 = __shfl_sync(0xFFFFFFFFu, dv,  se);
            if (e0 >= m) w0 = 0.f;
            uint2 a = y[s0 * 16 + lh];
            acc4_fp16(f0, f1, f2, f3, a, w0);
        }
    }
    // fold the two half-warps (each covered a disjoint edge subset)
    f0 += __shfl_xor_sync(0xFFFFFFFFu, f0, 16);
    f1 += __shfl_xor_sync(0xFFFFFFFFu, f1, 16);
    f2 += __shfl_xor_sync(0xFFFFFFFFu, f2, 16);
    f3 += __shfl_xor_sync(0xFFFFFFFFu, f3, 16);

    float diw = g_dinv[w];
    // self-loop term: y1[w] * dinv_w (total weight becomes dinv_w^2 = 1/deg)
    uint2 sv = y[w * 16 + lh];
    acc4_fp16(f0, f1, f2, f3, sv, diw);

    if (l < 16) {
        float4 bb = reinterpret_cast<const float4*>(b1)[lh];
        float4 hv;
        hv.x = fmaxf(fmaf(diw, f0, bb.x), 0.f);
        hv.y = fmaxf(fmaf(diw, f1, bb.y), 0.f);
        hv.z = fmaxf(fmaf(diw, f2, bb.z), 0.f);
        hv.w = fmaxf(fmaf(diw, f3, bb.w), 0.f);
        reinterpret_cast<float4*>(g_h)[w * 16 + lh] = hv;
    }
}

// ---------------------------------------------------------------------------
// GEMM2: y2h[n,48] = fp16((h[n,64] @ W2pad[64,48]) * dinv[row]), col 47 = 0
// ---------------------------------------------------------------------------
#define HS_LD 65
__global__ __launch_bounds__(192) void gemm2_kernel(const float* __restrict__ W2, int n) {
    __shared__ float Ws[F_HID * F_OUTP];      // 12 KB, [k][c]
    __shared__ float Hs[64 * HS_LD];          // ~16.6 KB, [r][k] padded
    int tid = threadIdx.x;
    int row0 = blockIdx.x * 64;

    for (int i = tid; i < F_HID * F_OUTP; i += 192) {
        int k = i / F_OUTP, c = i - k * F_OUTP;
        Ws[i] = (c < F_OUT) ? W2[k * F_OUT + c] : 0.f;
    }
    for (int i = tid; i < 64 * F_HID; i += 192) {
        int r = i >> 6, k = i & 63;
        int gr = row0 + r;
        Hs[r * HS_LD + k] = (gr < n) ? g_h[gr * F_HID + k] : 0.f;
    }
    __syncthreads();

    int tx = tid % 12;        // cols tx*4..tx*4+3
    int ty = tid / 12;        // 0..15, rows ty*4..ty*4+3
    float4 acc[4];
    #pragma unroll
    for (int i = 0; i < 4; i++) acc[i] = make_float4(0.f, 0.f, 0.f, 0.f);
    const float4* Ws4 = reinterpret_cast<const float4*>(Ws);

    #pragma unroll 4
    for (int k = 0; k < F_HID; k++) {
        float4 wv = Ws4[k * 12 + tx];
        #pragma unroll
        for (int i = 0; i < 4; i++) {
            float a = Hs[(ty * 4 + i) * HS_LD + k];
            acc[i].x = fmaf(a, wv.x, acc[i].x);
            acc[i].y = fmaf(a, wv.y, acc[i].y);
            acc[i].z = fmaf(a, wv.z, acc[i].z);
            acc[i].w = fmaf(a, wv.w, acc[i].w);
        }
    }
    uint2* yp = reinterpret_cast<uint2*>(g_y2h);   // 12 uint2 per row
    #pragma unroll
    for (int i = 0; i < 4; i++) {
        int r = row0 + ty * 4 + i;
        if (r < n) {
            float di = g_dinv[r];
            float4 v = acc[i];
            __half2 p0 = __floats2half2_rn(v.x * di, v.y * di);
            __half2 p1 = __floats2half2_rn(v.z * di, v.w * di);
            uint2 u;
            u.x = *reinterpret_cast<unsigned int*>(&p0);
            u.y = *reinterpret_cast<unsigned int*>(&p1);
            yp[r * 12 + tx] = u;
        }
    }
}

// ---------------------------------------------------------------------------
// Aggregation layer 2 + bias + log_softmax (warp per node, fp16 gathers,
// unroll 4 — same loop shape as the R5 version that measured well):
//   z[d] = dinv[d]*(sum y2[s] + y2[d]) + b2 ; out = z - logsumexp(z)
// ---------------------------------------------------------------------------
__global__ __launch_bounds__(256) void agg2_kernel(const float* __restrict__ b2,
                                                   float* __restrict__ out, int n) {
    int w = (blockIdx.x * blockDim.x + threadIdx.x) >> 5;
    int l = threadIdx.x & 31;
    if (w >= n) return;
    const __half2* y = reinterpret_cast<const __half2*>(g_y2h);   // 24 per row
    bool act = (l < 24);
    int lc = act ? l : 0;

    float2 acc = make_float2(0.f, 0.f);
    if (act) {
        float2 v = __half22float2(y[w * 24 + l]);
        acc = v;                                   // self term (y2 pre-scaled)
    }
    int beg = g_off[w], end = g_off[w + 1];
    for (int j = beg; j < end; j += 32) {
        int m = min(32, end - j);
        int idx = (l < m) ? g_csrc[j + l] : 0;
        int t = 0;
        for (; t + 3 < m; t += 4) {
            int s0 = __shfl_sync(0xFFFFFFFFu, idx, t    );
            int s1 = __shfl_sync(0xFFFFFFFFu, idx, t + 1);
            int s2 = __shfl_sync(0xFFFFFFFFu, idx, t + 2);
            int s3 = __shfl_sync(0xFFFFFFFFu, idx, t + 3);
            if (act) {
                float2 v0 = __half22float2(y[s0 * 24 + lc]);
                float2 v1 = __half22float2(y[s1 * 24 + lc]);
                float2 v2 = __half22float2(y[s2 * 24 + lc]);
                float2 v3 = __half22float2(y[s3 * 24 + lc]);
                acc.x += (v0.x + v1.x) + (v2.x + v3.x);
                acc.y += (v0.y + v1.y) + (v2.y + v3.y);
            }
        }
        for (; t < m; t++) {
            int s0 = __shfl_sync(0xFFFFFFFFu, idx, t);
            if (act) {
                float2 v = __half22float2(y[s0 * 24 + lc]);
                acc.x += v.x; acc.y += v.y;
            }
        }
    }

    float di = g_dinv[w];
    float vx = -3.0e38f, vy = -3.0e38f;
    if (act) {
        vx = fmaf(di, acc.x, b2[2 * l]);
        if (2 * l + 1 < F_OUT) vy = fmaf(di, acc.y, b2[2 * l + 1]);
    }
    float m = fmaxf(vx, vy);
    #pragma unroll
    for (int o = 16; o > 0; o >>= 1)
        m = fmaxf(m, __shfl_xor_sync(0xFFFFFFFFu, m, o));
    float s = 0.f;
    if (act) {
        s = expf(vx - m);
        if (2 * l + 1 < F_OUT) s += expf(vy - m);
    }
    #pragma unroll
    for (int o = 16; o > 0; o >>= 1)
        s += __shfl_xor_sync(0xFFFFFFFFu, s, o);
    float lse = m + logf(s);

    if (act) {
        out[w * F_OUT + 2 * l] = vx - lse;
        if (2 * l + 1 < F_OUT) out[w * F_OUT + 2 * l + 1] = vy - lse;
    }
}

// ---------------------------------------------------------------------------
// Launch (R5 structure: gemm1 forked to side stream, joins before agg1)
// ---------------------------------------------------------------------------
extern "C" void kernel_launch(void* const* d_in, const int* in_sizes, int n_in,
                              void* d_out, int out_size) {
    const float* x  = (const float*)d_in[0];
    const int*   ei = (const int*)  d_in[1];
    const float* W1 = (const float*)d_in[2];
    const float* b1 = (const float*)d_in[3];
    const float* W2 = (const float*)d_in[4];
    const float* b2 = (const float*)d_in[5];
    float* out = (float*)d_out;

    int n = in_sizes[0] / F_IN;       // 100000
    int e = in_sizes[1] / 2;          // 1600000
    const int* src = ei;
    const int* dst = ei + e;

    static cudaStream_t s2 = nullptr;
    static cudaEvent_t ev_fork = nullptr, ev_join = nullptr;
    if (s2 == nullptr) {
        cudaStreamCreateWithFlags(&s2, cudaStreamNonBlocking);
        cudaEventCreateWithFlags(&ev_fork, cudaEventDisableTiming);
        cudaEventCreateWithFlags(&ev_join, cudaEventDisableTiming);
    }

    const int B = 256;
    int nb = (n + SCAN_TPB - 1) / SCAN_TPB;   // 196 <= SCAN_TPB

    // Fork: GEMM1 (independent of CSR build) on side stream
    cudaEventRecord(ev_fork, 0);
    cudaStreamWaitEvent(s2, ev_fork, 0);
    gemm1_kernel<<<(n + 31) / 32, 256, 0, s2>>>(x, W1, n);
    cudaEventRecord(ev_join, s2);

    // Main stream: CSR build
    zero_degi_kernel<<<(n + B - 1) / B, B>>>(n);
    count_kernel<<<(e + B - 1) / B, B>>>(dst, e);
    scan_partial_kernel<<<nb, SCAN_TPB>>>(n);
    scan_write_kernel<<<nb, SCAN_TPB>>>(n, e);
    fill_kernel<<<(e + B - 1) / B, B>>>(src, dst, e);

    // Join: agg1 needs CSR (main) and y1 (s2)
    cudaStreamWaitEvent(0, ev_join, 0);

    agg1_kernel<<<(n * 32 + B - 1) / B, B>>>(b1, n);
    gemm2_kernel<<<(n + 63) / 64, 192>>>(W2, n);
    agg2_kernel<<<(n * 32 + B - 1) / B, B>>>(b2, out, n);
}